// round 8
// baseline (speedup 1.0000x reference)
#include <cuda_runtime.h>
#include <cstdint>

#define EPSB 1e-5f
#define BATCH 4
#define HWN 65536        // H*W
#define NS 16384         // sampled points per batch
#define KN 16
#define TPB 256
#define ROWS 512         // rows per block-iteration (= 32 samples), 64 rows/warp
#define ITERS 2048       // BATCH*NS*KN / ROWS
#define FS 76            // feat/h stride in words (76%32=12 -> conflict-free A frags)
#define S01 72           // W0/W1 row stride (72%32=8 -> conflict-free B frags)
#define S2  136          // W2 row stride (136%32=8)

// ---- shared layout (floats) ----
#define OFF_W0 0
#define OFF_W1 (OFF_W0 + 72*S01)       // W0: 72(k) x 72
#define OFF_W2 (OFF_W1 + 64*S01)       // W1: 64 x 72
#define OFF_B0 (OFF_W2 + 64*S2)        // W2: 64 x 136
#define OFF_B1 (OFF_B0 + 64)
#define OFF_B2 (OFF_B1 + 64)
#define OFF_FEAT (OFF_B2 + 128)
#define SMEM_FLOATS (OFF_FEAT + ROWS*FS)   // 48392 floats = 193568 B

// Folded + tf32-rounded weights (biases kept fp32)
__device__ float g_w0f[67*64];
__device__ float g_b0f[64];
__device__ float g_w1f[64*64];
__device__ float g_b1f[64];
__device__ float g_w2f[64*128];
__device__ float g_b2f[128];

__device__ __forceinline__ uint32_t tf32r(float x) {
    uint32_t r;
    asm("cvt.rna.tf32.f32 %0, %1;" : "=r"(r) : "f"(x));
    return r;
}

__global__ void fold_bn_kernel(
    const float* __restrict__ w0, const float* __restrict__ b0,
    const float* __restrict__ gg0, const float* __restrict__ be0,
    const float* __restrict__ m0, const float* __restrict__ v0,
    const float* __restrict__ w1, const float* __restrict__ b1,
    const float* __restrict__ gg1, const float* __restrict__ be1,
    const float* __restrict__ m1, const float* __restrict__ v1,
    const float* __restrict__ w2, const float* __restrict__ b2,
    const float* __restrict__ gg2, const float* __restrict__ be2,
    const float* __restrict__ m2, const float* __restrict__ v2)
{
    int i = blockIdx.x * blockDim.x + threadIdx.x;
    if (i < 67*64) { int o = i & 63;  float s = gg0[o]*rsqrtf(v0[o]+EPSB);
                     g_w0f[i] = __uint_as_float(tf32r(w0[i]*s)); }
    if (i < 64*64) { int o = i & 63;  float s = gg1[o]*rsqrtf(v1[o]+EPSB);
                     g_w1f[i] = __uint_as_float(tf32r(w1[i]*s)); }
    if (i < 64*128){ int o = i & 127; float s = gg2[o]*rsqrtf(v2[o]+EPSB);
                     g_w2f[i] = __uint_as_float(tf32r(w2[i]*s)); }
    if (i < 64) {
        float s0 = gg0[i]*rsqrtf(v0[i]+EPSB); g_b0f[i] = (b0[i]-m0[i])*s0 + be0[i];
        float s1 = gg1[i]*rsqrtf(v1[i]+EPSB); g_b1f[i] = (b1[i]-m1[i])*s1 + be1[i];
    }
    if (i < 128) {
        float s2 = gg2[i]*rsqrtf(v2[i]+EPSB); g_b2f[i] = (b2[i]-m2[i])*s2 + be2[i];
    }
}

// One tf32 mma.m16n8k8, accumulators in-place.
__device__ __forceinline__ void mma_tf32(float (&d)[4],
                                         uint32_t a0, uint32_t a1, uint32_t a2, uint32_t a3,
                                         uint32_t b0, uint32_t b1)
{
    asm volatile(
        "mma.sync.aligned.m16n8k8.row.col.f32.tf32.tf32.f32 "
        "{%0,%1,%2,%3}, {%4,%5,%6,%7}, {%8,%9}, {%0,%1,%2,%3};"
        : "+f"(d[0]), "+f"(d[1]), "+f"(d[2]), "+f"(d[3])
        : "r"(a0), "r"(a1), "r"(a2), "r"(a3), "r"(b0), "r"(b1));
}

// GEMM: this warp's MT*16 rows (A, row-major stride FS) x B[k][bcol+n] (stride BS).
// KS k-steps of 8; NT n-tiles of 8; MT m-tiles of 16. Bias offset bcol too.
template<int KS, int NT, int MT>
__device__ __forceinline__ void gemm_layer(const uint32_t* __restrict__ A,
                                           const uint32_t* __restrict__ B, int BS, int bcol,
                                           const float* __restrict__ bias,
                                           float (&acc)[MT][NT][4], int g, int t)
{
    #pragma unroll
    for (int mt = 0; mt < MT; mt++)
        #pragma unroll
        for (int nt = 0; nt < NT; nt++) {
            float bz0 = bias[bcol + nt*8 + 2*t];
            float bz1 = bias[bcol + nt*8 + 2*t + 1];
            acc[mt][nt][0] = bz0; acc[mt][nt][1] = bz1;
            acc[mt][nt][2] = bz0; acc[mt][nt][3] = bz1;
        }
    #pragma unroll
    for (int ks = 0; ks < KS; ks++) {
        const int kb = ks * 8;
        uint32_t a[MT][4];
        #pragma unroll
        for (int mt = 0; mt < MT; mt++) {
            const uint32_t* Ar = A + (mt*16) * FS;
            a[mt][0] = Ar[(g    )*FS + kb + t    ];
            a[mt][1] = Ar[(g + 8)*FS + kb + t    ];
            a[mt][2] = Ar[(g    )*FS + kb + t + 4];
            a[mt][3] = Ar[(g + 8)*FS + kb + t + 4];
        }
        #pragma unroll
        for (int nt = 0; nt < NT; nt++) {
            uint32_t b0 = B[(kb + t    )*BS + bcol + nt*8 + g];
            uint32_t b1 = B[(kb + t + 4)*BS + bcol + nt*8 + g];
            #pragma unroll
            for (int mt = 0; mt < MT; mt++)
                mma_tf32(acc[mt][nt], a[mt][0], a[mt][1], a[mt][2], a[mt][3], b0, b1);
        }
    }
}

// relu + tf32-round + write back to this warp's rows (in place, cols 0..NT*8-1)
template<int NT, int MT>
__device__ __forceinline__ void writeback(uint32_t* __restrict__ A,
                                          float (&acc)[MT][NT][4], int g, int t)
{
    #pragma unroll
    for (int mt = 0; mt < MT; mt++) {
        uint32_t* Ar = A + (mt*16) * FS;
        #pragma unroll
        for (int nt = 0; nt < NT; nt++) {
            const int col = nt*8 + 2*t;
            Ar[(g    )*FS + col    ] = tf32r(fmaxf(acc[mt][nt][0], 0.f));
            Ar[(g    )*FS + col + 1] = tf32r(fmaxf(acc[mt][nt][1], 0.f));
            Ar[(g + 8)*FS + col    ] = tf32r(fmaxf(acc[mt][nt][2], 0.f));
            Ar[(g + 8)*FS + col + 1] = tf32r(fmaxf(acc[mt][nt][3], 0.f));
        }
    }
}

__global__ __launch_bounds__(TPB, 1)
void psa_mma_kernel(const float* __restrict__ xyz_proj,
                    const float* __restrict__ points_proj,
                    const float* __restrict__ xyz_sampled,
                    const int*   __restrict__ neighbor_idx,
                    const float* __restrict__ valid_mask,
                    float* __restrict__ out, int dup)
{
    extern __shared__ float sm[];
    const float* b0s = sm + OFF_B0;
    const float* b1s = sm + OFF_B1;
    const float* b2s = sm + OFF_B2;
    uint32_t* featU = (uint32_t*)(sm + OFF_FEAT);
    const uint32_t* W0 = (const uint32_t*)(sm + OFF_W0);
    const uint32_t* W1 = (const uint32_t*)(sm + OFF_W1);
    const uint32_t* W2 = (const uint32_t*)(sm + OFF_W2);

    const int tid  = threadIdx.x;
    const int warp = tid >> 5;
    const int lane = tid & 31;
    const int g = lane >> 2;   // group id (row within tile)
    const int t = lane & 3;    // thread in group (col within tile)

    // ---- stage folded weights (once per block; zero-pad K rows / N cols) ----
    for (int i = tid; i < 72*S01; i += TPB) {
        int k = i / S01, n = i - k*S01;
        sm[OFF_W0 + i] = (k < 67 && n < 64) ? g_w0f[k*64 + n] : 0.f;
    }
    for (int i = tid; i < 64*S01; i += TPB) {
        int k = i / S01, n = i - k*S01;
        sm[OFF_W1 + i] = (n < 64) ? g_w1f[k*64 + n] : 0.f;
    }
    for (int i = tid; i < 64*S2; i += TPB) {
        int k = i / S2, n = i - k*S2;
        sm[OFF_W2 + i] = (n < 128) ? g_w2f[k*128 + n] : 0.f;
    }
    if (tid < 64)  { sm[OFF_B0 + tid] = g_b0f[tid]; sm[OFF_B1 + tid] = g_b1f[tid]; }
    if (tid < 128) { sm[OFF_B2 + tid] = g_b2f[tid]; }
    __syncthreads();

    uint32_t* Awarp = featU + (warp * 64) * FS;   // this warp's 64 rows

    for (int it = blockIdx.x; it < ITERS; it += gridDim.x) {
        __syncwarp();   // prior iter's A reads done before gather overwrite

        // -------- gather + feature build: 2 rows per thread (warp-private) --------
        #pragma unroll
        for (int rr = 0; rr < 2; rr++) {
            const int row  = warp*64 + rr*32 + lane;  // 0..511, owned by this warp
            const int flat = it * 32 + (row >> 4);    // global sample 0..65535
            const int b = flat >> 14;
            const int k = row & 15;
            const int gi = flat * KN + k;
            const int nb = __ldg(neighbor_idx + gi);
            const float m = __ldg(valid_mask + gi);

            uint32_t* fr = featU + row * FS;
            const float* xp = xyz_proj + ((size_t)(b * HWN + nb)) * 3;
            const float* ct = xyz_sampled + (size_t)flat * 3;
            fr[0] = tf32r(__ldg(xp + 0) * m - __ldg(ct + 0));
            fr[1] = tf32r(__ldg(xp + 1) * m - __ldg(ct + 1));
            fr[2] = tf32r(__ldg(xp + 2) * m - __ldg(ct + 2));

            const float4* pp = (const float4*)(points_proj + ((size_t)(b * HWN + nb)) * 64);
            #pragma unroll
            for (int c4 = 0; c4 < 16; c4++) {
                float4 p = __ldg(pp + c4);
                const int cb = 3 + 4*c4;
                fr[cb+0] = tf32r(p.x * m);
                fr[cb+1] = tf32r(p.y * m);
                fr[cb+2] = tf32r(p.z * m);
                fr[cb+3] = tf32r(p.w * m);
            }
            #pragma unroll
            for (int c = 67; c < 72; c++) fr[c] = 0u;  // K pad for layer 0
        }
        __syncwarp();

        // ---------------- layer 0: 72(K) -> 64 ----------------
        {
            float acc[4][8][4];
            gemm_layer<9, 8, 4>(Awarp, W0, S01, 0, b0s, acc, g, t);
            writeback<8, 4>(Awarp, acc, g, t);
        }
        __syncwarp();

        // ---------------- layer 1: 64 -> 64 ----------------
        {
            float acc[4][8][4];
            gemm_layer<8, 8, 4>(Awarp, W1, S01, 0, b1s, acc, g, t);
            writeback<8, 4>(Awarp, acc, g, t);
        }
        __syncwarp();

        // ------- layer 2: 64 -> 128 in two 64-col passes + relu + K-maxpool + store -------
        #pragma unroll
        for (int p = 0; p < 2; p++) {
            float acc[4][8][4];
            gemm_layer<8, 8, 4>(Awarp, W2, S2, p*64, b2s, acc, g, t);

            #pragma unroll
            for (int mt = 0; mt < 4; mt++) {
                const int smp = it * 32 + warp * 4 + mt;   // global sample
                #pragma unroll
                for (int nt = 0; nt < 8; nt++) {
                    float v0 = fmaxf(fmaxf(acc[mt][nt][0], 0.f), fmaxf(acc[mt][nt][2], 0.f));
                    float v1 = fmaxf(fmaxf(acc[mt][nt][1], 0.f), fmaxf(acc[mt][nt][3], 0.f));
                    v0 = fmaxf(v0, __shfl_xor_sync(0xffffffffu, v0, 4));
                    v1 = fmaxf(v1, __shfl_xor_sync(0xffffffffu, v1, 4));
                    v0 = fmaxf(v0, __shfl_xor_sync(0xffffffffu, v0, 8));
                    v1 = fmaxf(v1, __shfl_xor_sync(0xffffffffu, v1, 8));
                    v0 = fmaxf(v0, __shfl_xor_sync(0xffffffffu, v0, 16));
                    v1 = fmaxf(v1, __shfl_xor_sync(0xffffffffu, v1, 16));
                    if (g == 0) {   // lanes t=0..3 cover cols p*64 + nt*8 + {0,2,4,6}(+1)
                        const int col = p*64 + nt*8 + 2*t;
                        float2 val = make_float2(v0, v1);
                        *(float2*)(out + (size_t)smp*128 + col) = val;
                        if (dup)
                            *(float2*)(out + (size_t)(BATCH*NS)*128 + (size_t)smp*128 + col) = val;
                    }
                }
            }
        }
    }
}

extern "C" void kernel_launch(void* const* d_in, const int* in_sizes, int n_in,
                              void* d_out, int out_size) {
    const float* xyz_proj    = (const float*)d_in[0];
    const float* points_proj = (const float*)d_in[1];
    const float* xyz_sampled = (const float*)d_in[2];
    const int*   neighbor_idx= (const int*)d_in[3];
    const float* valid_mask  = (const float*)d_in[4];

    const float* w0 = (const float*)d_in[5];
    const float* b0 = (const float*)d_in[6];
    const float* g0 = (const float*)d_in[7];
    const float* be0= (const float*)d_in[8];
    const float* m0 = (const float*)d_in[9];
    const float* v0 = (const float*)d_in[10];
    const float* w1 = (const float*)d_in[11];
    const float* b1 = (const float*)d_in[12];
    const float* g1 = (const float*)d_in[13];
    const float* be1= (const float*)d_in[14];
    const float* m1 = (const float*)d_in[15];
    const float* v1 = (const float*)d_in[16];
    const float* w2 = (const float*)d_in[17];
    const float* b2 = (const float*)d_in[18];
    const float* g2 = (const float*)d_in[19];
    const float* be2= (const float*)d_in[20];
    const float* m2 = (const float*)d_in[21];
    const float* v2 = (const float*)d_in[22];

    float* out = (float*)d_out;

    static int s_grid = 0;
    static const int smem_bytes = SMEM_FLOATS * (int)sizeof(float);
    if (s_grid == 0) {
        int sms = 0;
        cudaDeviceGetAttribute(&sms, cudaDevAttrMultiProcessorCount, 0);
        if (sms <= 0) sms = 148;
        cudaFuncSetAttribute(psa_mma_kernel, cudaFuncAttributeMaxDynamicSharedMemorySize, smem_bytes);
        s_grid = (sms < ITERS) ? sms : ITERS;
    }

    fold_bn_kernel<<<(64*128 + 255) / 256, 256>>>(
        w0, b0, g0, be0, m0, v0,
        w1, b1, g1, be1, m1, v1,
        w2, b2, g2, be2, m2, v2);

    const long long total = (long long)BATCH * NS * 128;
    const int dup = ((long long)out_size >= 2 * total) ? 1 : 0;

    psa_mma_kernel<<<s_grid, TPB, smem_bytes>>>(
        xyz_proj, points_proj, xyz_sampled, neighbor_idx, valid_mask, out, dup);
}

// round 12
// speedup vs baseline: 1.4440x; 1.4440x over previous
#include <cuda_runtime.h>
#include <cstdint>

#define EPSB 1e-5f
#define BATCH 4
#define HWN 65536        // H*W
#define NS 16384         // sampled points per batch
#define KN 16
#define TPB 256
#define ROWS 256         // rows per block-iteration (= 16 samples)
#define ITERS 4096       // BATCH*NS*KN / ROWS
#define FS 76            // feat/h stride in words (76%32=12 -> conflict-free A frags)
#define S01 72           // W0/W1 row stride (72%32=8 -> conflict-free B frags)
#define S2  136          // W2 row stride (136%32=8)

// ---- shared layout (floats) ----
#define OFF_W0 0
#define OFF_W1 (OFF_W0 + 72*S01)       // W0: 72(k) x 72
#define OFF_W2 (OFF_W1 + 64*S01)       // W1: 64 x 72
#define OFF_B0 (OFF_W2 + 64*S2)        // W2: 64 x 136
#define OFF_B1 (OFF_B0 + 64)
#define OFF_B2 (OFF_B1 + 64)
#define OFF_FEAT (OFF_B2 + 128)
#define SMEM_FLOATS (OFF_FEAT + ROWS*FS)   // 38208 floats = 152832 B

// Folded + tf32-rounded weights (biases kept fp32)
__device__ float g_w0f[67*64];
__device__ float g_b0f[64];
__device__ float g_w1f[64*64];
__device__ float g_b1f[64];
__device__ float g_w2f[64*128];
__device__ float g_b2f[128];

__device__ __forceinline__ uint32_t tf32r(float x) {
    uint32_t r;
    asm("cvt.rna.tf32.f32 %0, %1;" : "=r"(r) : "f"(x));
    return r;
}

__global__ void fold_bn_kernel(
    const float* __restrict__ w0, const float* __restrict__ b0,
    const float* __restrict__ gg0, const float* __restrict__ be0,
    const float* __restrict__ m0, const float* __restrict__ v0,
    const float* __restrict__ w1, const float* __restrict__ b1,
    const float* __restrict__ gg1, const float* __restrict__ be1,
    const float* __restrict__ m1, const float* __restrict__ v1,
    const float* __restrict__ w2, const float* __restrict__ b2,
    const float* __restrict__ gg2, const float* __restrict__ be2,
    const float* __restrict__ m2, const float* __restrict__ v2)
{
    int i = blockIdx.x * blockDim.x + threadIdx.x;
    if (i < 67*64) { int o = i & 63;  float s = gg0[o]*rsqrtf(v0[o]+EPSB);
                     g_w0f[i] = __uint_as_float(tf32r(w0[i]*s)); }
    if (i < 64*64) { int o = i & 63;  float s = gg1[o]*rsqrtf(v1[o]+EPSB);
                     g_w1f[i] = __uint_as_float(tf32r(w1[i]*s)); }
    if (i < 64*128){ int o = i & 127; float s = gg2[o]*rsqrtf(v2[o]+EPSB);
                     g_w2f[i] = __uint_as_float(tf32r(w2[i]*s)); }
    if (i < 64) {
        float s0 = gg0[i]*rsqrtf(v0[i]+EPSB); g_b0f[i] = (b0[i]-m0[i])*s0 + be0[i];
        float s1 = gg1[i]*rsqrtf(v1[i]+EPSB); g_b1f[i] = (b1[i]-m1[i])*s1 + be1[i];
    }
    if (i < 128) {
        float s2 = gg2[i]*rsqrtf(v2[i]+EPSB); g_b2f[i] = (b2[i]-m2[i])*s2 + be2[i];
    }
}

// One tf32 mma.m16n8k8, accumulators in-place.
__device__ __forceinline__ void mma_tf32(float (&d)[4],
                                         uint32_t a0, uint32_t a1, uint32_t a2, uint32_t a3,
                                         uint32_t b0, uint32_t b1)
{
    asm volatile(
        "mma.sync.aligned.m16n8k8.row.col.f32.tf32.tf32.f32 "
        "{%0,%1,%2,%3}, {%4,%5,%6,%7}, {%8,%9}, {%0,%1,%2,%3};"
        : "+f"(d[0]), "+f"(d[1]), "+f"(d[2]), "+f"(d[3])
        : "r"(a0), "r"(a1), "r"(a2), "r"(a3), "r"(b0), "r"(b1));
}

// GEMM layer: this warp's 32 rows (A, row-major stride FS) x B[k][n] (stride BS).
// KS k-steps of 8; NT n-tiles of 8. acc[mt][nt][4] initialized with bias.
template<int KS, int NT>
__device__ __forceinline__ void gemm_layer(const uint32_t* __restrict__ A,
                                           const uint32_t* __restrict__ B, int BS,
                                           const float* __restrict__ bias,
                                           float (&acc)[2][NT][4], int g, int t)
{
    #pragma unroll
    for (int mt = 0; mt < 2; mt++)
        #pragma unroll
        for (int nt = 0; nt < NT; nt++) {
            float bz0 = bias[nt*8 + 2*t];
            float bz1 = bias[nt*8 + 2*t + 1];
            acc[mt][nt][0] = bz0; acc[mt][nt][1] = bz1;
            acc[mt][nt][2] = bz0; acc[mt][nt][3] = bz1;
        }
    #pragma unroll
    for (int ks = 0; ks < KS; ks++) {
        const int kb = ks * 8;
        uint32_t a[2][4];
        #pragma unroll
        for (int mt = 0; mt < 2; mt++) {
            const uint32_t* Ar = A + (mt*16) * FS;
            a[mt][0] = Ar[(g    )*FS + kb + t    ];
            a[mt][1] = Ar[(g + 8)*FS + kb + t    ];
            a[mt][2] = Ar[(g    )*FS + kb + t + 4];
            a[mt][3] = Ar[(g + 8)*FS + kb + t + 4];
        }
        #pragma unroll
        for (int nt = 0; nt < NT; nt++) {
            uint32_t b0 = B[(kb + t    )*BS + nt*8 + g];
            uint32_t b1 = B[(kb + t + 4)*BS + nt*8 + g];
            mma_tf32(acc[0][nt], a[0][0], a[0][1], a[0][2], a[0][3], b0, b1);
            mma_tf32(acc[1][nt], a[1][0], a[1][1], a[1][2], a[1][3], b0, b1);
        }
    }
}

// relu + tf32-round + write back to this warp's rows (in place, cols 0..63)
template<int NT>
__device__ __forceinline__ void writeback(uint32_t* __restrict__ A,
                                          float (&acc)[2][NT][4], int g, int t)
{
    #pragma unroll
    for (int mt = 0; mt < 2; mt++) {
        uint32_t* Ar = A + (mt*16) * FS;
        #pragma unroll
        for (int nt = 0; nt < NT; nt++) {
            const int col = nt*8 + 2*t;
            Ar[(g    )*FS + col    ] = tf32r(fmaxf(acc[mt][nt][0], 0.f));
            Ar[(g    )*FS + col + 1] = tf32r(fmaxf(acc[mt][nt][1], 0.f));
            Ar[(g + 8)*FS + col    ] = tf32r(fmaxf(acc[mt][nt][2], 0.f));
            Ar[(g + 8)*FS + col + 1] = tf32r(fmaxf(acc[mt][nt][3], 0.f));
        }
    }
}

__global__ __launch_bounds__(TPB, 1)
void psa_mma_kernel(const float* __restrict__ xyz_proj,
                    const float* __restrict__ points_proj,
                    const float* __restrict__ xyz_sampled,
                    const int*   __restrict__ neighbor_idx,
                    const float* __restrict__ valid_mask,
                    float* __restrict__ out, int dup)
{
    extern __shared__ float sm[];
    const float* b0s = sm + OFF_B0;
    const float* b1s = sm + OFF_B1;
    const float* b2s = sm + OFF_B2;
    uint32_t* featU = (uint32_t*)(sm + OFF_FEAT);
    const uint32_t* W0 = (const uint32_t*)(sm + OFF_W0);
    const uint32_t* W1 = (const uint32_t*)(sm + OFF_W1);
    const uint32_t* W2 = (const uint32_t*)(sm + OFF_W2);

    const int tid  = threadIdx.x;
    const int warp = tid >> 5;
    const int lane = tid & 31;
    const int g = lane >> 2;   // group id (row within tile)
    const int t = lane & 3;    // thread in group (col within tile)

    // ---- stage folded weights (once per block) ----
    // Feature word layout per row: [d0,d1,d2, 0(pad), p0..p63, 0,0,0,0]
    // So W0's K rows are permuted to match: k<3 -> xyz rows, k==3 -> zero,
    // 4<=k<68 -> points rows (k-1), k>=68 -> zero.
    for (int i = tid; i < 72*S01; i += TPB) {
        int k = i / S01, n = i - k*S01;
        float v = 0.f;
        if (n < 64) {
            if (k < 3)               v = g_w0f[k*64 + n];
            else if (k >= 4 && k < 68) v = g_w0f[(k-1)*64 + n];
        }
        sm[OFF_W0 + i] = v;
    }
    for (int i = tid; i < 64*S01; i += TPB) {
        int k = i / S01, n = i - k*S01;
        sm[OFF_W1 + i] = (n < 64) ? g_w1f[k*64 + n] : 0.f;
    }
    for (int i = tid; i < 64*S2; i += TPB) {
        int k = i / S2, n = i - k*S2;
        sm[OFF_W2 + i] = (n < 128) ? g_w2f[k*128 + n] : 0.f;
    }
    if (tid < 64)  { sm[OFF_B0 + tid] = g_b0f[tid]; sm[OFF_B1 + tid] = g_b1f[tid]; }
    if (tid < 128) { sm[OFF_B2 + tid] = g_b2f[tid]; }
    __syncthreads();

    uint32_t* Awarp = featU + (warp * 32) * FS;   // this warp's 32 rows

    const int sub  = lane & 7;   // 16B-quad within a row segment
    const int rsel = lane >> 3;  // which of 4 rows per cooperative load

    for (int it = blockIdx.x; it < ITERS; it += gridDim.x) {
        __syncwarp();   // prior iter's A reads done before gather overwrite

        // ---------------- gather + feature build (warp-cooperative) ----------------
        {
            // per-lane row bookkeeping (lane = row within warp)
            const int row  = warp*32 + lane;          // 0..255
            const int flat = it * 16 + (row >> 4);    // global sample 0..65535
            const int b = flat >> 14;                 // warp-uniform (sample pairs never straddle batches)
            const int k = row & 15;
            const int gi = flat * KN + k;
            const int nb = __ldg(neighbor_idx + gi);
            const float m = __ldg(valid_mask + gi);

            uint32_t* fr = featU + row * FS;
            const float* xp = xyz_proj + ((size_t)(b * HWN + nb)) * 3;
            const float* ct = xyz_sampled + (size_t)flat * 3;
            fr[0] = tf32r(__ldg(xp + 0) * m - __ldg(ct + 0));
            fr[1] = tf32r(__ldg(xp + 1) * m - __ldg(ct + 1));
            fr[2] = tf32r(__ldg(xp + 2) * m - __ldg(ct + 2));
            fr[3] = 0u;                                  // pad (zero W0 row)
            *(uint4*)(fr + 68) = make_uint4(0u,0u,0u,0u); // K pad to 72

            // cooperative points gather: 8 lanes x 16B cover a 128B row half;
            // one LDG.128 touches 4 lines (4 rows), one STS.128 is 4x128B contiguous.
            #pragma unroll
            for (int rg = 0; rg < 8; rg++) {
                const int rl = rg*4 + rsel;   // row 0..31 within warp
                const int nb_r = __shfl_sync(0xffffffffu, nb, rl);
                const float m_r = __shfl_sync(0xffffffffu, m, rl);
                const float4* pr = (const float4*)(points_proj + ((size_t)(b * HWN + nb_r)) * 64);
                uint32_t* frr = featU + (warp*32 + rl) * FS + 4;
                #pragma unroll
                for (int h = 0; h < 2; h++) {
                    float4 p = __ldg(pr + sub + h*8);
                    uint4 q;
                    q.x = tf32r(p.x * m_r);
                    q.y = tf32r(p.y * m_r);
                    q.z = tf32r(p.z * m_r);
                    q.w = tf32r(p.w * m_r);
                    *(uint4*)(frr + (sub + h*8)*4) = q;
                }
            }
        }
        __syncwarp();

        // ---------------- layer 0: 72(K) -> 64 ----------------
        {
            float acc[2][8][4];
            gemm_layer<9, 8>(Awarp, W0, S01, b0s, acc, g, t);
            writeback<8>(Awarp, acc, g, t);
        }
        __syncwarp();

        // ---------------- layer 1: 64 -> 64 ----------------
        {
            float acc[2][8][4];
            gemm_layer<8, 8>(Awarp, W1, S01, b1s, acc, g, t);
            writeback<8>(Awarp, acc, g, t);
        }
        __syncwarp();

        // ---------------- layer 2: 64 -> 128 + relu + K-maxpool + store ----------------
        {
            float acc[2][16][4];
            gemm_layer<8, 16>(Awarp, W2, S2, b2s, acc, g, t);

            #pragma unroll
            for (int mt = 0; mt < 2; mt++) {
                const int smp = it * 16 + warp * 2 + mt;   // global sample
                #pragma unroll
                for (int nt = 0; nt < 16; nt++) {
                    float v0 = fmaxf(fmaxf(acc[mt][nt][0], 0.f), fmaxf(acc[mt][nt][2], 0.f));
                    float v1 = fmaxf(fmaxf(acc[mt][nt][1], 0.f), fmaxf(acc[mt][nt][3], 0.f));
                    v0 = fmaxf(v0, __shfl_xor_sync(0xffffffffu, v0, 4));
                    v1 = fmaxf(v1, __shfl_xor_sync(0xffffffffu, v1, 4));
                    v0 = fmaxf(v0, __shfl_xor_sync(0xffffffffu, v0, 8));
                    v1 = fmaxf(v1, __shfl_xor_sync(0xffffffffu, v1, 8));
                    v0 = fmaxf(v0, __shfl_xor_sync(0xffffffffu, v0, 16));
                    v1 = fmaxf(v1, __shfl_xor_sync(0xffffffffu, v1, 16));
                    if (g == 0) {   // lanes 0..3 cover cols nt*8 + {0,2,4,6}(+1)
                        const int col = nt*8 + 2*t;
                        float2 val = make_float2(v0, v1);
                        *(float2*)(out + (size_t)smp*128 + col) = val;
                        if (dup)
                            *(float2*)(out + (size_t)(BATCH*NS)*128 + (size_t)smp*128 + col) = val;
                    }
                }
            }
        }
    }
}

extern "C" void kernel_launch(void* const* d_in, const int* in_sizes, int n_in,
                              void* d_out, int out_size) {
    const float* xyz_proj    = (const float*)d_in[0];
    const float* points_proj = (const float*)d_in[1];
    const float* xyz_sampled = (const float*)d_in[2];
    const int*   neighbor_idx= (const int*)d_in[3];
    const float* valid_mask  = (const float*)d_in[4];

    const float* w0 = (const float*)d_in[5];
    const float* b0 = (const float*)d_in[6];
    const float* g0 = (const float*)d_in[7];
    const float* be0= (const float*)d_in[8];
    const float* m0 = (const float*)d_in[9];
    const float* v0 = (const float*)d_in[10];
    const float* w1 = (const float*)d_in[11];
    const float* b1 = (const float*)d_in[12];
    const float* g1 = (const float*)d_in[13];
    const float* be1= (const float*)d_in[14];
    const float* m1 = (const float*)d_in[15];
    const float* v1 = (const float*)d_in[16];
    const float* w2 = (const float*)d_in[17];
    const float* b2 = (const float*)d_in[18];
    const float* g2 = (const float*)d_in[19];
    const float* be2= (const float*)d_in[20];
    const float* m2 = (const float*)d_in[21];
    const float* v2 = (const float*)d_in[22];

    float* out = (float*)d_out;

    static int s_grid = 0;
    static const int smem_bytes = SMEM_FLOATS * (int)sizeof(float);
    if (s_grid == 0) {
        int sms = 0;
        cudaDeviceGetAttribute(&sms, cudaDevAttrMultiProcessorCount, 0);
        if (sms <= 0) sms = 148;
        cudaFuncSetAttribute(psa_mma_kernel, cudaFuncAttributeMaxDynamicSharedMemorySize, smem_bytes);
        s_grid = (sms < ITERS) ? sms : ITERS;
    }

    fold_bn_kernel<<<(64*128 + 255) / 256, 256>>>(
        w0, b0, g0, be0, m0, v0,
        w1, b1, g1, be1, m1, v1,
        w2, b2, g2, be2, m2, v2);

    const long long total = (long long)BATCH * NS * 128;
    const int dup = ((long long)out_size >= 2 * total) ? 1 : 0;

    psa_mma_kernel<<<s_grid, TPB, smem_bytes>>>(
        xyz_proj, points_proj, xyz_sampled, neighbor_idx, valid_mask, out, dup);
}